// round 1
// baseline (speedup 1.0000x reference)
#include <cuda_runtime.h>
#include <math_constants.h>

// Problem dims (fixed by the dataset)
#define M_DIM 16384
#define N_DIM 4096
#define K_DIM 256
#define NQ    31      // boundaries per column

// GEMM tiling
#define BM 128
#define BN 128
#define BK 16

__global__ void __launch_bounds__(256)
eidetic_linear_kernel(const float* __restrict__ X,     // [M, K]
                      const float* __restrict__ W,     // [N, K]
                      const float* __restrict__ bias,  // [N]
                      const float* __restrict__ Q,     // [N, NQ] sorted asc
                      float* __restrict__ out,         // [M, N]
                      float* __restrict__ idxf)        // [M, N]
{
    __shared__ float As[BK][BM];        // 8 KB  (k-major -> m contiguous)
    __shared__ float Bs[BK][BN];        // 8 KB
    __shared__ float qs[BN][32];        // 16 KB (31 bounds + INF pad)

    const int tid = threadIdx.x;
    const int bm  = blockIdx.y * BM;
    const int bn  = blockIdx.x * BN;

    const int ty = tid >> 4;   // 0..15 -> m sub-tile
    const int tx = tid & 15;   // 0..15 -> n sub-tile

    float acc[8][8];
    #pragma unroll
    for (int i = 0; i < 8; i++)
        #pragma unroll
        for (int j = 0; j < 8; j++) acc[i][j] = 0.f;

    // Each block loads a 128x16 tile of A and of B per k-step.
    // 512 float4 per tile, 256 threads -> 2 float4 each.
    const int f0 = tid, f1 = tid + 256;
    const int r0 = f0 >> 2, c0 = (f0 & 3) * 4;
    const int r1 = f1 >> 2, c1 = (f1 & 3) * 4;

    for (int k0 = 0; k0 < K_DIM; k0 += BK) {
        float4 va0 = *(const float4*)(X + (size_t)(bm + r0) * K_DIM + k0 + c0);
        float4 va1 = *(const float4*)(X + (size_t)(bm + r1) * K_DIM + k0 + c1);
        float4 vb0 = *(const float4*)(W + (size_t)(bn + r0) * K_DIM + k0 + c0);
        float4 vb1 = *(const float4*)(W + (size_t)(bn + r1) * K_DIM + k0 + c1);

        As[c0+0][r0] = va0.x; As[c0+1][r0] = va0.y; As[c0+2][r0] = va0.z; As[c0+3][r0] = va0.w;
        As[c1+0][r1] = va1.x; As[c1+1][r1] = va1.y; As[c1+2][r1] = va1.z; As[c1+3][r1] = va1.w;
        Bs[c0+0][r0] = vb0.x; Bs[c0+1][r0] = vb0.y; Bs[c0+2][r0] = vb0.z; Bs[c0+3][r0] = vb0.w;
        Bs[c1+0][r1] = vb1.x; Bs[c1+1][r1] = vb1.y; Bs[c1+2][r1] = vb1.z; Bs[c1+3][r1] = vb1.w;

        __syncthreads();

        #pragma unroll
        for (int kk = 0; kk < BK; kk++) {
            float a[8], b[8];
            *(float4*)(a)     = *(const float4*)&As[kk][ty * 8];
            *(float4*)(a + 4) = *(const float4*)&As[kk][ty * 8 + 4];
            *(float4*)(b)     = *(const float4*)&Bs[kk][tx * 8];
            *(float4*)(b + 4) = *(const float4*)&Bs[kk][tx * 8 + 4];
            #pragma unroll
            for (int i = 0; i < 8; i++)
                #pragma unroll
                for (int j = 0; j < 8; j++)
                    acc[i][j] = fmaf(a[i], b[j], acc[i][j]);
        }
        __syncthreads();
    }

    // ---- Epilogue: stage this block's quantile rows into smem ----
    for (int i = tid; i < BN * NQ; i += 256) {
        int c = i / NQ;
        int r = i - c * NQ;
        qs[c][r] = Q[(size_t)(bn + c) * NQ + r];
    }
    if (tid < BN) qs[tid][31] = CUDART_INF_F;   // pad so uniform search covers 32
    __syncthreads();

    float bvals[8];
    #pragma unroll
    for (int j = 0; j < 8; j++) bvals[j] = bias[bn + tx * 8 + j];

    #pragma unroll
    for (int i = 0; i < 8; i++) {
        const int m = bm + ty * 8 + i;
        float ovals[8], ivals[8];
        #pragma unroll
        for (int j = 0; j < 8; j++) {
            const float v  = acc[i][j];
            const float* qc = qs[tx * 8 + j];
            // branchless lower_bound over 32 (count of bounds < v); qc[31]=INF
            int pos = 0;
            if (qc[15]      < v) pos = 16;
            if (qc[pos + 7] < v) pos += 8;
            if (qc[pos + 3] < v) pos += 4;
            if (qc[pos + 1] < v) pos += 2;
            if (qc[pos]     < v) pos += 1;
            ovals[j] = v + bvals[j];
            ivals[j] = (float)pos;
        }
        const size_t off = (size_t)m * N_DIM + bn + tx * 8;
        *(float4*)(out  + off)     = make_float4(ovals[0], ovals[1], ovals[2], ovals[3]);
        *(float4*)(out  + off + 4) = make_float4(ovals[4], ovals[5], ovals[6], ovals[7]);
        *(float4*)(idxf + off)     = make_float4(ivals[0], ivals[1], ivals[2], ivals[3]);
        *(float4*)(idxf + off + 4) = make_float4(ivals[4], ivals[5], ivals[6], ivals[7]);
    }
}

extern "C" void kernel_launch(void* const* d_in, const int* in_sizes, int n_in,
                              void* d_out, int out_size)
{
    const float* x    = (const float*)d_in[0];  // [16384, 256]
    const float* w    = (const float*)d_in[1];  // [4096, 256]
    const float* bias = (const float*)d_in[2];  // [4096]
    const float* q    = (const float*)d_in[3];  // [4096, 31]

    float* out  = (float*)d_out;                          // [16384, 4096]
    float* idxf = out + (size_t)M_DIM * N_DIM;            // [16384, 4096]

    dim3 grid(N_DIM / BN, M_DIM / BM);   // (32, 128) = 4096 blocks
    eidetic_linear_kernel<<<grid, 256>>>(x, w, bias, q, out, idxf);
}

// round 4
// speedup vs baseline: 2.9765x; 2.9765x over previous
#include <cuda_runtime.h>
#include <cuda_bf16.h>
#include <cstdint>

// Problem dims
#define M_DIM 16384
#define N_DIM 4096
#define K_DIM 256
#define KE    768        // expanded K: X'=[hi|hi|lo], W'=[hi|lo|hi]
#define NQ    31

// GEMM tiling
#define BM 128
#define BN 128
#define BK 64            // bf16 per chunk = 128 bytes per row
#define NCHUNK (KE / BK) // 12

// bf16-split scratch (device globals: allocation-free scratch)
__device__ __nv_bfloat16 g_Xp[(size_t)M_DIM * KE];   // ~25 MB
__device__ __nv_bfloat16 g_Wp[(size_t)N_DIM * KE];   // ~6 MB

// ---- dynamic smem layout (bytes) ----
#define OFF_A0   0          // 128x64 bf16 = 16384
#define OFF_A1   16384
#define OFF_B0   32768
#define OFF_B1   49152
#define OFF_QS   65536      // 128 cols x 33 f32 = 16896
#define OFF_BB   82432      // 128 f32 = 512
#define SMEM_BYTES 82944

__device__ __forceinline__ uint32_t smem_u32(const void* p) {
    uint32_t a;
    asm("{ .reg .u64 t; cvta.to.shared.u64 t, %1; cvt.u32.u64 %0, t; }" : "=r"(a) : "l"(p));
    return a;
}
__device__ __forceinline__ uint32_t sw128(uint32_t off) {   // SW128 within a tile
    return off ^ ((off >> 3) & 0x70);
}
__device__ __forceinline__ void cp_async16(uint32_t dst, const void* src) {
    asm volatile("cp.async.cg.shared.global [%0], [%1], 16;" :: "r"(dst), "l"(src) : "memory");
}
__device__ __forceinline__ void cp_commit() {
    asm volatile("cp.async.commit_group;" ::: "memory");
}
template <int N>
__device__ __forceinline__ void cp_wait() {
    asm volatile("cp.async.wait_group %0;" :: "n"(N) : "memory");
}
__device__ __forceinline__ void ldmatrix_x4(uint32_t* r, uint32_t addr) {
    asm volatile("ldmatrix.sync.aligned.m8n8.x4.shared.b16 {%0,%1,%2,%3}, [%4];"
                 : "=r"(r[0]), "=r"(r[1]), "=r"(r[2]), "=r"(r[3]) : "r"(addr));
}
__device__ __forceinline__ void mma16816(float* d, const uint32_t* a, const uint32_t* b) {
    asm volatile(
        "mma.sync.aligned.m16n8k16.row.col.f32.bf16.bf16.f32 "
        "{%0,%1,%2,%3}, {%4,%5,%6,%7}, {%8,%9}, {%0,%1,%2,%3};"
        : "+f"(d[0]), "+f"(d[1]), "+f"(d[2]), "+f"(d[3])
        : "r"(a[0]), "r"(a[1]), "r"(a[2]), "r"(a[3]), "r"(b[0]), "r"(b[1]));
}

// ================= kernel 1: fp32 -> bf16 hi/lo expansion =================
__global__ void __launch_bounds__(256)
convert_kernel(const float* __restrict__ X, const float* __restrict__ W)
{
    int i = blockIdx.x * blockDim.x + threadIdx.x;   // covers M_DIM*K_DIM
    {
        float x = X[i];
        __nv_bfloat16 hi = __float2bfloat16(x);
        __nv_bfloat16 lo = __float2bfloat16(x - __bfloat162float(hi));
        int m = i >> 8, k = i & 255;
        size_t base = (size_t)m * KE;
        g_Xp[base + k]       = hi;
        g_Xp[base + 256 + k] = hi;
        g_Xp[base + 512 + k] = lo;
    }
    if (i < N_DIM * K_DIM) {
        float w = W[i];
        __nv_bfloat16 hi = __float2bfloat16(w);
        __nv_bfloat16 lo = __float2bfloat16(w - __bfloat162float(hi));
        int n = i >> 8, k = i & 255;
        size_t base = (size_t)n * KE;
        g_Wp[base + k]       = hi;   // pairs with x_hi -> hi*hi
        g_Wp[base + 256 + k] = lo;   // pairs with x_hi -> hi*lo
        g_Wp[base + 512 + k] = hi;   // pairs with x_lo -> lo*hi
    }
}

// ================= kernel 2: HMMA GEMM + fused epilogue =================
extern __shared__ char smem[];

__device__ __forceinline__ int qsearch(const float* qc, float v) {
    int pos = 0;                 // lower_bound over 31 sorted bounds
    if (qc[15]      < v) pos = 16;
    if (pos + 7 < 31 ? (qc[pos + 7] < v) : false) pos += 8;
    else if (pos == 16) { /* qc[23] handled above */ }
    return pos;
}

__global__ void __launch_bounds__(256)
gemm_kernel(const float* __restrict__ bias, const float* __restrict__ Q,
            float* __restrict__ out, float* __restrict__ idxf)
{
    const int tid  = threadIdx.x;
    const int wid  = tid >> 5;
    const int lane = tid & 31;
    const int bm = blockIdx.y * BM;
    const int bn = blockIdx.x * BN;
    const uint32_t sb = smem_u32(smem);

    float* qs = (float*)(smem + OFF_QS);   // [128][33]
    float* bb = (float*)(smem + OFF_BB);   // [128]

    // stage quantiles (stride-33 pad) + bias
    for (int i = tid; i < BN * NQ; i += 256) {
        int n = i / NQ, r = i - n * NQ;
        qs[n * 33 + r] = Q[(size_t)(bn + n) * NQ + r];
    }
    if (tid < BN) bb[tid] = bias[bn + tid];

    // --- cp.async tile loaders: 1024 x 16B per tile, 4 per thread ---
    const char* gA = (const char*)(g_Xp + (size_t)bm * KE);
    const char* gB = (const char*)(g_Wp + (size_t)bn * KE);

    auto issue = [&](int c) {
        const int b = c & 1;
        const uint32_t aB = sb + (b ? OFF_A1 : OFF_A0);
        const uint32_t bB = sb + (b ? OFF_B1 : OFF_B0);
        const char* pa = gA + c * 128;
        const char* pb = gB + c * 128;
        #pragma unroll
        for (int t = 0; t < 4; ++t) {
            int i = tid + t * 256; int r = i >> 3, q = i & 7;
            uint32_t d = sw128((uint32_t)(r * 128 + q * 16));
            cp_async16(aB + d, pa + (size_t)r * (KE * 2) + q * 16);
        }
        #pragma unroll
        for (int t = 0; t < 4; ++t) {
            int i = tid + t * 256; int r = i >> 3, q = i & 7;
            uint32_t d = sw128((uint32_t)(r * 128 + q * 16));
            cp_async16(bB + d, pb + (size_t)r * (KE * 2) + q * 16);
        }
        cp_commit();
    };

    // warp layout: 4 (m) x 2 (n); warp tile 32 x 64
    const int wm = wid >> 1;
    const int wn = wid & 1;
    const int g  = lane >> 2;    // group id 0..7
    const int t4 = lane & 3;

    // ldmatrix lane address components (within-tile, before swizzle)
    // A (.x4): row = mBase + (lane & 15); kbyte = (lane >= 16) ? 16 : 0
    const int a_row_off = lane & 15;
    const int a_k_off   = (lane >> 4) << 4;
    // B (.x4): row(n) = nBase + (lane & 7) + ((lane & 16) ? 8 : 0); kbyte = ((lane >> 3) & 1) * 16
    const int b_row_off = (lane & 7) + ((lane & 16) ? 8 : 0);
    const int b_k_off   = ((lane >> 3) & 1) << 4;

    float acc[2][8][4];
    #pragma unroll
    for (int im = 0; im < 2; im++)
        #pragma unroll
        for (int in = 0; in < 8; in++)
            #pragma unroll
            for (int r = 0; r < 4; r++) acc[im][in][r] = 0.f;

    issue(0);

    for (int c = 0; c < NCHUNK; ++c) {
        if (c + 1 < NCHUNK) { issue(c + 1); cp_wait<1>(); }
        else                { cp_wait<0>(); }
        __syncthreads();

        const int b = c & 1;
        const uint32_t aB = sb + (b ? OFF_A1 : OFF_A0);
        const uint32_t bB = sb + (b ? OFF_B1 : OFF_B0);

        #pragma unroll
        for (int ks = 0; ks < 4; ++ks) {
            const int kb = ks * 32;   // byte offset of k-step (16 bf16 = 32B)
            uint32_t afr[2][4], bfr[4][4];
            #pragma unroll
            for (int im = 0; im < 2; im++) {
                uint32_t off = (uint32_t)((wm * 32 + im * 16 + a_row_off) * 128 + kb + a_k_off);
                ldmatrix_x4(afr[im], aB + sw128(off));
            }
            #pragma unroll
            for (int ib = 0; ib < 4; ib++) {
                uint32_t off = (uint32_t)((wn * 64 + ib * 16 + b_row_off) * 128 + kb + b_k_off);
                ldmatrix_x4(bfr[ib], bB + sw128(off));
            }
            #pragma unroll
            for (int im = 0; im < 2; im++)
                #pragma unroll
                for (int in = 0; in < 8; in++)
                    mma16816(acc[im][in], afr[im], bfr[in >> 1] + (in & 1) * 2);
        }
        __syncthreads();
    }

    // ---- epilogue: bias + searchsorted from registers, float2 stores ----
    #pragma unroll
    for (int in = 0; in < 8; in++) {
        const int col_l = wn * 64 + in * 8 + t4 * 2;       // local col (pair base)
        const float* q0 = qs + col_l * 33;
        const float* q1 = q0 + 33;
        const float bz0 = bb[col_l], bz1 = bb[col_l + 1];
        #pragma unroll
        for (int im = 0; im < 2; im++) {
            #pragma unroll
            for (int half = 0; half < 2; half++) {
                const int row = bm + wm * 32 + im * 16 + g + half * 8;
                const float v0 = acc[im][in][half * 2];
                const float v1 = acc[im][in][half * 2 + 1];
                int p0 = 0, p1 = 0;
                if (q0[15]     < v0) p0 = 16;
                if (p0 + 7 < NQ && q0[p0 + 7] < v0) p0 += 8;
                if (p0 + 3 < NQ && q0[p0 + 3] < v0) p0 += 4;
                if (p0 + 1 < NQ && q0[p0 + 1] < v0) p0 += 2;
                if (p0     < NQ && q0[p0]     < v0) p0 += 1;
                if (q1[15]     < v1) p1 = 16;
                if (p1 + 7 < NQ && q1[p1 + 7] < v1) p1 += 8;
                if (p1 + 3 < NQ && q1[p1 + 3] < v1) p1 += 4;
                if (p1 + 1 < NQ && q1[p1 + 1] < v1) p1 += 2;
                if (p1     < NQ && q1[p1]     < v1) p1 += 1;
                const size_t off = (size_t)row * N_DIM + bn + col_l;
                *(float2*)(out  + off) = make_float2(v0 + bz0, v1 + bz1);
                *(float2*)(idxf + off) = make_float2((float)p0, (float)p1);
            }
        }
    }
}

// ================= launch =================
extern "C" void kernel_launch(void* const* d_in, const int* in_sizes, int n_in,
                              void* d_out, int out_size)
{
    const float* x    = (const float*)d_in[0];  // [16384, 256]
    const float* w    = (const float*)d_in[1];  // [4096, 256]
    const float* bias = (const float*)d_in[2];  // [4096]
    const float* q    = (const float*)d_in[3];  // [4096, 31]

    float* out  = (float*)d_out;
    float* idxf = out + (size_t)M_DIM * N_DIM;

    cudaFuncSetAttribute(gemm_kernel, cudaFuncAttributeMaxDynamicSharedMemorySize, SMEM_BYTES);

    convert_kernel<<<(M_DIM * K_DIM) / 256, 256>>>(x, w);
    dim3 grid(N_DIM / BN, M_DIM / BM);   // (32, 128) = 4096 blocks
    gemm_kernel<<<grid, 256, SMEM_BYTES>>>(bias, q, out, idxf);
}